// round 15
// baseline (speedup 1.0000x reference)
#include <cuda_runtime.h>

// R14 base (NV=2, packed f32x2, 256thr x 2 blocks/SM = 16 warps, split ports)
// with W2 further split: rows u<32 of each MLP's W2 via __constant__ (LDC port),
// rows u>=32 + B2 + encoder + FC via shared (L1 port). Three-way port balance:
// L1 ~118us, const ~93us, fma ~149us (binding).

#define NTHREADS 256
#define NV 2

typedef unsigned long long u64;

// ---- constant-memory weights (float4 units) ----
#define cL1W   0
#define cL1B   16
#define cM1W1  20
#define cM1B1  276
#define cL2W   292
#define cL2B   308
#define cM2W1  312
#define cM2B1  568
#define cM1W2H 584   // m1_w2 rows 0..31 (512 floats = 128 f4)
#define cM2W2H 712   // m2_w2 rows 0..31
#define CW_F4  840

__constant__ float4 CW[CW_F4];

// ---- shared memory layout (floats): encoder + FC + W2(second half)/B2 ----
#define JE_W1 0      // 80
#define JE_B1 80     // 16
#define JE_W2 96     // 256
#define JE_B2 352    // 16
#define MU_W1 368    // 80
#define MU_B1 448    // 16
#define MU_W2 464    // 256
#define MU_B2 720    // 16
#define FC_W1 736    // 2048
#define FC_B1 2784   // 64
#define FC_W2 2848   // 64
#define M1_W2 2912   // 1024 (full; only rows 32..63 read from here)
#define M1_B2 3936   // 16
#define M2_W2 3952   // 1024
#define M2_B2 4976   // 16
#define SMEM_FLOATS 4992

struct Params {
    const float* x;
    const float* ea;
    const float* w[24];
    float* out;
    int G;
};

struct PackP { const float* src[10]; float* dst; };

__global__ void pack_kernel(PackP p)
{
    // lin1_w lin1_b m1_w1 m1_b1 lin2_w lin2_b m2_w1 m2_b1 m1_w2[0:512] m2_w2[0:512]
    const int sz[10]  = {64,16,1024,64, 64,16,1024,64, 512,512};
    const int off[10] = {0,64,80,1104, 1168,1232,1248,2272, 2336,2848};
    for (int a = 0; a < 10; a++) {
        const float* s = p.src[a];
        float* d = p.dst + off[a];
        for (int i = threadIdx.x; i < sz[a]; i += blockDim.x) d[i] = s[i];
    }
}

// ---- packed f32x2 helpers ----
__device__ __forceinline__ u64 pk(float lo, float hi) {
    u64 r; asm("mov.b64 %0,{%1,%2};" : "=l"(r) : "f"(lo), "f"(hi)); return r;
}
__device__ __forceinline__ void up(u64 v, float& lo, float& hi) {
    asm("mov.b64 {%0,%1},%2;" : "=f"(lo), "=f"(hi) : "l"(v));
}
__device__ __forceinline__ u64 f2(u64 a, u64 b, u64 c) {
    u64 d; asm("fma.rn.f32x2 %0,%1,%2,%3;" : "=l"(d) : "l"(a), "l"(b), "l"(c)); return d;
}
__device__ __forceinline__ u64 a2(u64 a, u64 b) {
    u64 d; asm("add.rn.f32x2 %0,%1,%2;" : "=l"(d) : "l"(a), "l"(b)); return d;
}
__device__ __forceinline__ u64 r2(u64 a) {
    float l, h; up(a, l, h);
    return pk(fmaxf(l, 0.f), fmaxf(h, 0.f));
}
__device__ __forceinline__ ulonglong2 ld2(const float* p) {
    return *reinterpret_cast<const ulonglong2*>(p);
}
__device__ __forceinline__ void cw2(int idx, u64& p0, u64& p1) {
    float4 v = CW[idx];
    p0 = pk(v.x, v.y);
    p1 = pk(v.z, v.w);
}

// one GINE layer + LN + relu for NV graphs.
// lin + W1/B1 + W2[rows<32] from __constant__; W2[rows>=32]/B2 from shared.
template<int LWo, int LBo, int W1o, int B1o, int W2Ho>
__device__ __forceinline__ void gineN(
    u64 h[NV][8], int lane, int node,
    const float* __restrict__ ea, const int* gc,
    const float* w2s, const float* b2s)
{
    u64 agg[NV][8];
#pragma unroll
    for (int nv = 0; nv < NV; nv++)
#pragma unroll
        for (int j = 0; j < 8; j++) agg[nv][j] = 0ull;

    // ---- message stage: weights hoisted across all 3 neighbors ----
    float ef[NV][3][4];
    int slv[3];
#pragma unroll
    for (int m = 1; m < 4; m++) {
        int src = (node + m) & 3;
        int eidx = src * 3 + node - (node > src ? 1 : 0);
        slv[m - 1] = (lane & ~3) | src;
#pragma unroll
        for (int nv = 0; nv < NV; nv++) {
            float4 e = __ldg(reinterpret_cast<const float4*>(
                ea + (long long)gc[nv] * 48 + eidx * 4));
            ef[nv][m-1][0] = e.x; ef[nv][m-1][1] = e.y;
            ef[nv][m-1][2] = e.z; ef[nv][m-1][3] = e.w;
        }
    }

#pragma unroll
    for (int v = 0; v < 4; v++) {
        u64 msg[NV][3][2];
        {
            u64 b0, b1; cw2(LBo + v, b0, b1);
#pragma unroll
            for (int nv = 0; nv < NV; nv++)
#pragma unroll
                for (int mm = 0; mm < 3; mm++) {
                    msg[nv][mm][0] = b0; msg[nv][mm][1] = b1;
                }
        }
#pragma unroll
        for (int k = 0; k < 4; k++) {
            u64 w0, w1; cw2(LWo + k * 4 + v, w0, w1);
#pragma unroll
            for (int mm = 0; mm < 3; mm++)
#pragma unroll
                for (int nv = 0; nv < NV; nv++) {
                    u64 ep = pk(ef[nv][mm][k], ef[nv][mm][k]);
                    msg[nv][mm][0] = f2(ep, w0, msg[nv][mm][0]);
                    msg[nv][mm][1] = f2(ep, w1, msg[nv][mm][1]);
                }
        }
#pragma unroll
        for (int mm = 0; mm < 3; mm++) {
            int sl = slv[mm];
#pragma unroll
            for (int nv = 0; nv < NV; nv++)
#pragma unroll
                for (int pr = 0; pr < 2; pr++) {
                    int j = 2 * v + pr;
                    u64 hs = __shfl_sync(0xffffffffu, h[nv][j], sl);
                    agg[nv][j] = a2(agg[nv][j], r2(a2(msg[nv][mm][pr], hs)));
                }
        }
    }

#pragma unroll
    for (int nv = 0; nv < NV; nv++)
#pragma unroll
        for (int j = 0; j < 8; j++) h[nv][j] = a2(h[nv][j], agg[nv][j]);

    // ---- MLP: W1/B1 const, W2 split const/shared, B2 shared ----
    u64 out[NV][8];
    {
        ulonglong2 a = ld2(b2s), b = ld2(b2s+4), c = ld2(b2s+8), d = ld2(b2s+12);
#pragma unroll
        for (int nv = 0; nv < NV; nv++) {
            out[nv][0]=a.x; out[nv][1]=a.y; out[nv][2]=b.x; out[nv][3]=b.y;
            out[nv][4]=c.x; out[nv][5]=c.y; out[nv][6]=d.x; out[nv][7]=d.y;
        }
    }

#pragma unroll
    for (int c = 0; c < 8; c++) {
        u64 hid[NV][4];
        {
            u64 b0, b1, b2v, b3;
            cw2(B1o + 2 * c, b0, b1);
            cw2(B1o + 2 * c + 1, b2v, b3);
#pragma unroll
            for (int nv = 0; nv < NV; nv++) {
                hid[nv][0] = b0; hid[nv][1] = b1; hid[nv][2] = b2v; hid[nv][3] = b3;
            }
        }
#pragma unroll
        for (int jp = 0; jp < 8; jp++) {
            u64 xlo[NV], xhi[NV];
#pragma unroll
            for (int nv = 0; nv < NV; nv++) {
                float a, b; up(h[nv][jp], a, b);
                xlo[nv] = pk(a, a); xhi[nv] = pk(b, b);
            }
#pragma unroll
            for (int t = 0; t < 2; t++) {
                int k = 2 * jp + t;
                u64 wv[4];
                cw2(W1o + k * 16 + 2 * c, wv[0], wv[1]);
                cw2(W1o + k * 16 + 2 * c + 1, wv[2], wv[3]);
#pragma unroll
                for (int nv = 0; nv < NV; nv++) {
                    u64 xp = t ? xhi[nv] : xlo[nv];
#pragma unroll
                    for (int v = 0; v < 4; v++)
                        hid[nv][v] = f2(xp, wv[v], hid[nv][v]);
                }
            }
        }
        // relu + second matmul: rows u<32 from const, u>=32 from shared
#pragma unroll
        for (int v = 0; v < 4; v++) {
            float s0[NV], s1[NV];
#pragma unroll
            for (int nv = 0; nv < NV; nv++) {
                float a, b; up(hid[nv][v], a, b);
                s0[nv] = fmaxf(a, 0.f); s1[nv] = fmaxf(b, 0.f);
            }
#pragma unroll
            for (int t = 0; t < 2; t++) {
                int u = c * 8 + 2 * v + t;
                u64 wv[8];
                if (c < 4) {
                    cw2(W2Ho + u * 4 + 0, wv[0], wv[1]);
                    cw2(W2Ho + u * 4 + 1, wv[2], wv[3]);
                    cw2(W2Ho + u * 4 + 2, wv[4], wv[5]);
                    cw2(W2Ho + u * 4 + 3, wv[6], wv[7]);
                } else {
                    const float* r = w2s + u * 16;
                    ulonglong2 wa = ld2(r), wb = ld2(r+4), wc = ld2(r+8), wd = ld2(r+12);
                    wv[0]=wa.x; wv[1]=wa.y; wv[2]=wb.x; wv[3]=wb.y;
                    wv[4]=wc.x; wv[5]=wc.y; wv[6]=wd.x; wv[7]=wd.y;
                }
#pragma unroll
                for (int nv = 0; nv < NV; nv++) {
                    float s = t ? s1[nv] : s0[nv];
                    u64 sp = pk(s, s);
#pragma unroll
                    for (int jj = 0; jj < 8; jj++)
                        out[nv][jj] = f2(sp, wv[jj], out[nv][jj]);
                }
            }
        }
    }

    // LayerNorm (ddof=0) + relu -> back into packed h
#pragma unroll
    for (int nv = 0; nv < NV; nv++) {
        float o[16];
#pragma unroll
        for (int j = 0; j < 8; j++) up(out[nv][j], o[2*j], o[2*j+1]);
        float mean = 0.f;
#pragma unroll
        for (int d = 0; d < 16; d++) mean += o[d];
        mean *= (1.f / 16.f);
        float var = 0.f;
#pragma unroll
        for (int d = 0; d < 16; d++) { float dd = o[d] - mean; var = fmaf(dd, dd, var); }
        var *= (1.f / 16.f);
        float inv = rsqrtf(var + 1e-5f);
#pragma unroll
        for (int j = 0; j < 8; j++)
            h[nv][j] = pk(fmaxf((o[2*j] - mean) * inv, 0.f),
                          fmaxf((o[2*j+1] - mean) * inv, 0.f));
    }
}

__global__ void __launch_bounds__(NTHREADS, 2)
gnn_kernel(Params p)
{
    __shared__ float S[SMEM_FLOATS];

    // stage encoder + FC + W2/B2 weights into shared
    {
        const int map[15]   = {0,1,2,3,4,5,6,7, 20,21,22, 12,13,18,19};
        const int sizes[15] = {80,16,256,16, 80,16,256,16, 2048,64,64,
                               1024,16,1024,16};
        const int offs[15]  = {JE_W1,JE_B1,JE_W2,JE_B2, MU_W1,MU_B1,MU_W2,MU_B2,
                               FC_W1,FC_B1,FC_W2, M1_W2,M1_B2,M2_W2,M2_B2};
        for (int a = 0; a < 15; a++) {
            const float* src = p.w[map[a]];
            float* dst = S + offs[a];
            int n = sizes[a];
            for (int i = threadIdx.x; i < n; i += NTHREADS) dst[i] = src[i];
        }
    }
    __syncthreads();

    int tid = threadIdx.x;
    int lane = tid & 31;
    int node = lane & 3;
    int group = lane >> 2;
    int warpG = (int)((blockIdx.x * (unsigned)NTHREADS + tid) >> 5);

    if (warpG * 16 >= p.G) return;   // warp-uniform

    int base = warpG * 16 + group;
    int gidx[NV], gc[NV];
    bool valid[NV];
#pragma unroll
    for (int nv = 0; nv < NV; nv++) {
        gidx[nv] = base + 8 * nv;
        valid[nv] = gidx[nv] < p.G;
        gc[nv] = valid[nv] ? gidx[nv] : (p.G - 1);
    }

    // ---- heterogeneous encoder (shared, node-divergent base) ----
    const float* w1p = (node == 3) ? (S + MU_W1) : (S + JE_W1);
    const float* b1p = (node == 3) ? (S + MU_B1) : (S + JE_B1);
    const float* w2p = (node == 3) ? (S + MU_W2) : (S + JE_W2);
    const float* b2p = (node == 3) ? (S + MU_B2) : (S + JE_B2);

    u64 h[NV][8];
    {
        float xin[NV][5];
#pragma unroll
        for (int nv = 0; nv < NV; nv++) {
            const float* xr = p.x + (long long)(gc[nv] * 4 + node) * 5;
#pragma unroll
            for (int k = 0; k < 5; k++) xin[nv][k] = __ldg(xr + k);
        }

        u64 tv[NV][8];
        {
            ulonglong2 a = ld2(b1p), b = ld2(b1p+4), c = ld2(b1p+8), d = ld2(b1p+12);
#pragma unroll
            for (int nv = 0; nv < NV; nv++) {
                tv[nv][0]=a.x; tv[nv][1]=a.y; tv[nv][2]=b.x; tv[nv][3]=b.y;
                tv[nv][4]=c.x; tv[nv][5]=c.y; tv[nv][6]=d.x; tv[nv][7]=d.y;
            }
        }
#pragma unroll
        for (int k = 0; k < 5; k++) {
            const float* r = w1p + k * 16;
            ulonglong2 wa = ld2(r), wb = ld2(r+4), wc = ld2(r+8), wd = ld2(r+12);
            u64 wv[8] = {wa.x,wa.y,wb.x,wb.y,wc.x,wc.y,wd.x,wd.y};
#pragma unroll
            for (int nv = 0; nv < NV; nv++) {
                u64 xp = pk(xin[nv][k], xin[nv][k]);
#pragma unroll
                for (int j = 0; j < 8; j++)
                    tv[nv][j] = f2(xp, wv[j], tv[nv][j]);
            }
        }

        {
            ulonglong2 a = ld2(b2p), b = ld2(b2p+4), c = ld2(b2p+8), d = ld2(b2p+12);
#pragma unroll
            for (int nv = 0; nv < NV; nv++) {
                h[nv][0]=a.x; h[nv][1]=a.y; h[nv][2]=b.x; h[nv][3]=b.y;
                h[nv][4]=c.x; h[nv][5]=c.y; h[nv][6]=d.x; h[nv][7]=d.y;
            }
        }
#pragma unroll
        for (int jp = 0; jp < 8; jp++) {
            u64 xlo[NV], xhi[NV];
#pragma unroll
            for (int nv = 0; nv < NV; nv++) {
                float a, b; up(tv[nv][jp], a, b);
                xlo[nv] = pk(fmaxf(a, 0.f), fmaxf(a, 0.f));
                xhi[nv] = pk(fmaxf(b, 0.f), fmaxf(b, 0.f));
            }
#pragma unroll
            for (int t = 0; t < 2; t++) {
                const float* r = w2p + (2 * jp + t) * 16;
                ulonglong2 wa = ld2(r), wb = ld2(r+4), wc = ld2(r+8), wd = ld2(r+12);
                u64 wv[8] = {wa.x,wa.y,wb.x,wb.y,wc.x,wc.y,wd.x,wd.y};
#pragma unroll
                for (int nv = 0; nv < NV; nv++) {
                    u64 xp = t ? xhi[nv] : xlo[nv];
#pragma unroll
                    for (int j = 0; j < 8; j++)
                        h[nv][j] = f2(xp, wv[j], h[nv][j]);
                }
            }
        }
    }

    // ---- two GINE blocks (three-way split-port weights) ----
    gineN<cL1W, cL1B, cM1W1, cM1B1, cM1W2H>(h, lane, node, p.ea, gc,
                                            S + M1_W2, S + M1_B2);
    gineN<cL2W, cL2B, cM2W1, cM2B1, cM2W2H>(h, lane, node, p.ea, gc,
                                            S + M2_W2, S + M2_B2);

    // ---- pooling (packed shfl) + LN ----
    float g[NV][32];
#pragma unroll
    for (int nv = 0; nv < NV; nv++) {
#pragma unroll
        for (int j = 0; j < 8; j++) {
            u64 s = h[nv][j];
            s = a2(s, __shfl_xor_sync(0xffffffffu, s, 1));
            s = a2(s, __shfl_xor_sync(0xffffffffu, s, 2));
            float sa, sb; up(s, sa, sb);
            g[nv][2*j]   = sa * 0.25f;
            g[nv][2*j+1] = sb * 0.25f;

            u64 mx = h[nv][j];
            u64 o1 = __shfl_xor_sync(0xffffffffu, mx, 1);
            float a0, b0, a1, b1; up(mx, a0, b0); up(o1, a1, b1);
            mx = pk(fmaxf(a0, a1), fmaxf(b0, b1));
            u64 o2 = __shfl_xor_sync(0xffffffffu, mx, 2);
            up(mx, a0, b0); up(o2, a1, b1);
            g[nv][16 + 2*j]   = fmaxf(a0, a1);
            g[nv][16 + 2*j+1] = fmaxf(b0, b1);
        }
        float mean = 0.f;
#pragma unroll
        for (int d = 0; d < 32; d++) mean += g[nv][d];
        mean *= (1.f / 32.f);
        float var = 0.f;
#pragma unroll
        for (int d = 0; d < 32; d++) { float dd = g[nv][d] - mean; var = fmaf(dd, dd, var); }
        var *= (1.f / 32.f);
        float inv = rsqrtf(var + 1e-5f);
#pragma unroll
        for (int d = 0; d < 32; d++) g[nv][d] = (g[nv][d] - mean) * inv;
    }

    // ---- FC head: 32 -> 64 -> 1; node-divergent slices from shared ----
    u64 av[NV][8];
    {
        const float* r = S + FC_B1 + node * 16;
        ulonglong2 a = ld2(r), b = ld2(r+4), c = ld2(r+8), d = ld2(r+12);
#pragma unroll
        for (int nv = 0; nv < NV; nv++) {
            av[nv][0]=a.x; av[nv][1]=a.y; av[nv][2]=b.x; av[nv][3]=b.y;
            av[nv][4]=c.x; av[nv][5]=c.y; av[nv][6]=d.x; av[nv][7]=d.y;
        }
    }
#pragma unroll
    for (int k = 0; k < 32; k++) {
        const float* r = S + FC_W1 + k * 64 + node * 16;
        ulonglong2 wa = ld2(r), wb = ld2(r+4), wc = ld2(r+8), wd = ld2(r+12);
        u64 wv[8] = {wa.x,wa.y,wb.x,wb.y,wc.x,wc.y,wd.x,wd.y};
#pragma unroll
        for (int nv = 0; nv < NV; nv++) {
            u64 gp = pk(g[nv][k], g[nv][k]);
#pragma unroll
            for (int j = 0; j < 8; j++) av[nv][j] = f2(gp, wv[j], av[nv][j]);
        }
    }
    float acc[NV] = {0.f, 0.f};
#pragma unroll
    for (int j = 0; j < 8; j++) {
        float2 w2v = *reinterpret_cast<const float2*>(S + FC_W2 + node * 16 + 2 * j);
#pragma unroll
        for (int nv = 0; nv < NV; nv++) {
            float a, b; up(av[nv][j], a, b);
            acc[nv] = fmaf(fmaxf(a, 0.f), w2v.x, acc[nv]);
            acc[nv] = fmaf(fmaxf(b, 0.f), w2v.y, acc[nv]);
        }
    }
    const float fcb2 = __ldg(p.w[23]);
#pragma unroll
    for (int nv = 0; nv < NV; nv++) {
        acc[nv] += __shfl_xor_sync(0xffffffffu, acc[nv], 1);
        acc[nv] += __shfl_xor_sync(0xffffffffu, acc[nv], 2);
        if (node == 0 && valid[nv])
            p.out[gidx[nv]] = acc[nv] + fcb2;
    }
}

extern "C" void kernel_launch(void* const* d_in, const int* in_sizes, int n_in,
                              void* d_out, int out_size)
{
    Params p;
    p.x  = (const float*)d_in[0];
    p.ea = (const float*)d_in[1];
    for (int i = 0; i < 24; i++) p.w[i] = (const float*)d_in[2 + i];
    p.out = (float*)d_out;
    p.G = in_sizes[0] / 20;            // x is [G*4, 5]

    // Fill constant bank via its global-space address (graph-capturable).
    void* cw_addr = nullptr;
    cudaGetSymbolAddress(&cw_addr, CW);
    PackP pp;
    pp.src[0] = (const float*)d_in[10];  // lin1_w
    pp.src[1] = (const float*)d_in[11];  // lin1_b
    pp.src[2] = (const float*)d_in[12];  // m1_w1
    pp.src[3] = (const float*)d_in[13];  // m1_b1
    pp.src[4] = (const float*)d_in[16];  // lin2_w
    pp.src[5] = (const float*)d_in[17];  // lin2_b
    pp.src[6] = (const float*)d_in[18];  // m2_w1
    pp.src[7] = (const float*)d_in[19];  // m2_b1
    pp.src[8] = (const float*)d_in[14];  // m1_w2 (first 512 floats used)
    pp.src[9] = (const float*)d_in[20];  // m2_w2 (first 512 floats used)
    pp.dst = (float*)cw_addr;
    pack_kernel<<<1, 256>>>(pp);

    // 16 graphs per warp, 8 warps per block -> 128 graphs per block
    int blocks = (p.G + 127) / 128;
    if (blocks < 1) blocks = 1;
    gnn_kernel<<<blocks, NTHREADS>>>(p);
}

// round 16
// speedup vs baseline: 1.0126x; 1.0126x over previous
#include <cuda_runtime.h>

// FINAL (champion, R14): NV=2 graphs/thread, packed f32x2 FFMA, 256thr x 2
// blocks/SM = 16 warps. MLP weight stream split across ports: lin + W1/B1 via
// __constant__ (LDC port, filled by a graph-capturable pack kernel through the
// symbol's global address); W2/B2 + encoder + FC via shared (L1 port).
// Warp = 8 groups of 4 lanes (lane&3 = node); group j handles graphs base+j
// and base+j+8. Messages via intra-group shuffles; pooling via packed shfl.

#define NTHREADS 256
#define NV 2

typedef unsigned long long u64;

// ---- constant-memory weights (float4 units): lin + W1/B1 only ----
#define cL1W  0
#define cL1B  16
#define cM1W1 20
#define cM1B1 276
#define cL2W  292
#define cL2B  308
#define cM2W1 312
#define cM2B1 568
#define CW_F4 584

__constant__ float4 CW[CW_F4];

// ---- shared memory layout (floats): encoder + FC + W2/B2 ----
#define JE_W1 0      // 80
#define JE_B1 80     // 16
#define JE_W2 96     // 256
#define JE_B2 352    // 16
#define MU_W1 368    // 80
#define MU_B1 448    // 16
#define MU_W2 464    // 256
#define MU_B2 720    // 16
#define FC_W1 736    // 2048
#define FC_B1 2784   // 64
#define FC_W2 2848   // 64
#define M1_W2 2912   // 1024
#define M1_B2 3936   // 16
#define M2_W2 3952   // 1024
#define M2_B2 4976   // 16
#define SMEM_FLOATS 4992

struct Params {
    const float* x;
    const float* ea;
    const float* w[24];
    float* out;
    int G;
};

struct PackP { const float* src[8]; float* dst; };

__global__ void pack_kernel(PackP p)
{
    // lin1_w lin1_b m1_w1 m1_b1 lin2_w lin2_b m2_w1 m2_b1
    const int sz[8]  = {64,16,1024,64, 64,16,1024,64};
    const int off[8] = {0,64,80,1104, 1168,1232,1248,2272};
    for (int a = 0; a < 8; a++) {
        const float* s = p.src[a];
        float* d = p.dst + off[a];
        for (int i = threadIdx.x; i < sz[a]; i += blockDim.x) d[i] = s[i];
    }
}

// ---- packed f32x2 helpers ----
__device__ __forceinline__ u64 pk(float lo, float hi) {
    u64 r; asm("mov.b64 %0,{%1,%2};" : "=l"(r) : "f"(lo), "f"(hi)); return r;
}
__device__ __forceinline__ void up(u64 v, float& lo, float& hi) {
    asm("mov.b64 {%0,%1},%2;" : "=f"(lo), "=f"(hi) : "l"(v));
}
__device__ __forceinline__ u64 f2(u64 a, u64 b, u64 c) {
    u64 d; asm("fma.rn.f32x2 %0,%1,%2,%3;" : "=l"(d) : "l"(a), "l"(b), "l"(c)); return d;
}
__device__ __forceinline__ u64 a2(u64 a, u64 b) {
    u64 d; asm("add.rn.f32x2 %0,%1,%2;" : "=l"(d) : "l"(a), "l"(b)); return d;
}
__device__ __forceinline__ u64 r2(u64 a) {
    float l, h; up(a, l, h);
    return pk(fmaxf(l, 0.f), fmaxf(h, 0.f));
}
__device__ __forceinline__ ulonglong2 ld2(const float* p) {
    return *reinterpret_cast<const ulonglong2*>(p);
}
__device__ __forceinline__ void cw2(int idx, u64& p0, u64& p1) {
    float4 v = CW[idx];
    p0 = pk(v.x, v.y);
    p1 = pk(v.z, v.w);
}

// one GINE layer + LN + relu for NV graphs.
// lin + W1/B1 from __constant__ (LDC); W2/B2 from shared (LDS).
template<int LWo, int LBo, int W1o, int B1o>
__device__ __forceinline__ void gineN(
    u64 h[NV][8], int lane, int node,
    const float* __restrict__ ea, const int* gc,
    const float* w2s, const float* b2s)
{
    u64 agg[NV][8];
#pragma unroll
    for (int nv = 0; nv < NV; nv++)
#pragma unroll
        for (int j = 0; j < 8; j++) agg[nv][j] = 0ull;

    // ---- message stage: weights hoisted across all 3 neighbors ----
    float ef[NV][3][4];
    int slv[3];
#pragma unroll
    for (int m = 1; m < 4; m++) {
        int src = (node + m) & 3;
        int eidx = src * 3 + node - (node > src ? 1 : 0);
        slv[m - 1] = (lane & ~3) | src;
#pragma unroll
        for (int nv = 0; nv < NV; nv++) {
            float4 e = __ldg(reinterpret_cast<const float4*>(
                ea + (long long)gc[nv] * 48 + eidx * 4));
            ef[nv][m-1][0] = e.x; ef[nv][m-1][1] = e.y;
            ef[nv][m-1][2] = e.z; ef[nv][m-1][3] = e.w;
        }
    }

#pragma unroll
    for (int v = 0; v < 4; v++) {
        u64 msg[NV][3][2];
        {
            u64 b0, b1; cw2(LBo + v, b0, b1);
#pragma unroll
            for (int nv = 0; nv < NV; nv++)
#pragma unroll
                for (int mm = 0; mm < 3; mm++) {
                    msg[nv][mm][0] = b0; msg[nv][mm][1] = b1;
                }
        }
#pragma unroll
        for (int k = 0; k < 4; k++) {
            u64 w0, w1; cw2(LWo + k * 4 + v, w0, w1);
#pragma unroll
            for (int mm = 0; mm < 3; mm++)
#pragma unroll
                for (int nv = 0; nv < NV; nv++) {
                    u64 ep = pk(ef[nv][mm][k], ef[nv][mm][k]);
                    msg[nv][mm][0] = f2(ep, w0, msg[nv][mm][0]);
                    msg[nv][mm][1] = f2(ep, w1, msg[nv][mm][1]);
                }
        }
#pragma unroll
        for (int mm = 0; mm < 3; mm++) {
            int sl = slv[mm];
#pragma unroll
            for (int nv = 0; nv < NV; nv++)
#pragma unroll
                for (int pr = 0; pr < 2; pr++) {
                    int j = 2 * v + pr;
                    u64 hs = __shfl_sync(0xffffffffu, h[nv][j], sl);
                    agg[nv][j] = a2(agg[nv][j], r2(a2(msg[nv][mm][pr], hs)));
                }
        }
    }

#pragma unroll
    for (int nv = 0; nv < NV; nv++)
#pragma unroll
        for (int j = 0; j < 8; j++) h[nv][j] = a2(h[nv][j], agg[nv][j]);

    // ---- MLP: W1/B1 from constant, W2/B2 from shared ----
    u64 out[NV][8];
    {
        ulonglong2 a = ld2(b2s), b = ld2(b2s+4), c = ld2(b2s+8), d = ld2(b2s+12);
#pragma unroll
        for (int nv = 0; nv < NV; nv++) {
            out[nv][0]=a.x; out[nv][1]=a.y; out[nv][2]=b.x; out[nv][3]=b.y;
            out[nv][4]=c.x; out[nv][5]=c.y; out[nv][6]=d.x; out[nv][7]=d.y;
        }
    }

#pragma unroll
    for (int c = 0; c < 8; c++) {
        u64 hid[NV][4];
        {
            u64 b0, b1, b2v, b3;
            cw2(B1o + 2 * c, b0, b1);
            cw2(B1o + 2 * c + 1, b2v, b3);
#pragma unroll
            for (int nv = 0; nv < NV; nv++) {
                hid[nv][0] = b0; hid[nv][1] = b1; hid[nv][2] = b2v; hid[nv][3] = b3;
            }
        }
#pragma unroll
        for (int jp = 0; jp < 8; jp++) {
            u64 xlo[NV], xhi[NV];
#pragma unroll
            for (int nv = 0; nv < NV; nv++) {
                float a, b; up(h[nv][jp], a, b);
                xlo[nv] = pk(a, a); xhi[nv] = pk(b, b);
            }
#pragma unroll
            for (int t = 0; t < 2; t++) {
                int k = 2 * jp + t;
                u64 wv[4];
                cw2(W1o + k * 16 + 2 * c, wv[0], wv[1]);
                cw2(W1o + k * 16 + 2 * c + 1, wv[2], wv[3]);
#pragma unroll
                for (int nv = 0; nv < NV; nv++) {
                    u64 xp = t ? xhi[nv] : xlo[nv];
#pragma unroll
                    for (int v = 0; v < 4; v++)
                        hid[nv][v] = f2(xp, wv[v], hid[nv][v]);
                }
            }
        }
        // relu + second matmul (weights from shared)
#pragma unroll
        for (int v = 0; v < 4; v++) {
            float s0[NV], s1[NV];
#pragma unroll
            for (int nv = 0; nv < NV; nv++) {
                float a, b; up(hid[nv][v], a, b);
                s0[nv] = fmaxf(a, 0.f); s1[nv] = fmaxf(b, 0.f);
            }
#pragma unroll
            for (int t = 0; t < 2; t++) {
                int u = c * 8 + 2 * v + t;
                const float* r = w2s + u * 16;
                ulonglong2 wa = ld2(r), wb = ld2(r+4), wc = ld2(r+8), wd = ld2(r+12);
                u64 wv[8] = {wa.x, wa.y, wb.x, wb.y, wc.x, wc.y, wd.x, wd.y};
#pragma unroll
                for (int nv = 0; nv < NV; nv++) {
                    float s = t ? s1[nv] : s0[nv];
                    u64 sp = pk(s, s);
#pragma unroll
                    for (int jj = 0; jj < 8; jj++)
                        out[nv][jj] = f2(sp, wv[jj], out[nv][jj]);
                }
            }
        }
    }

    // LayerNorm (ddof=0) + relu -> back into packed h
#pragma unroll
    for (int nv = 0; nv < NV; nv++) {
        float o[16];
#pragma unroll
        for (int j = 0; j < 8; j++) up(out[nv][j], o[2*j], o[2*j+1]);
        float mean = 0.f;
#pragma unroll
        for (int d = 0; d < 16; d++) mean += o[d];
        mean *= (1.f / 16.f);
        float var = 0.f;
#pragma unroll
        for (int d = 0; d < 16; d++) { float dd = o[d] - mean; var = fmaf(dd, dd, var); }
        var *= (1.f / 16.f);
        float inv = rsqrtf(var + 1e-5f);
#pragma unroll
        for (int j = 0; j < 8; j++)
            h[nv][j] = pk(fmaxf((o[2*j] - mean) * inv, 0.f),
                          fmaxf((o[2*j+1] - mean) * inv, 0.f));
    }
}

__global__ void __launch_bounds__(NTHREADS, 2)
gnn_kernel(Params p)
{
    __shared__ float S[SMEM_FLOATS];

    // stage encoder + FC + W2/B2 weights into shared
    {
        const int map[15]   = {0,1,2,3,4,5,6,7, 20,21,22, 12,13,18,19};
        const int sizes[15] = {80,16,256,16, 80,16,256,16, 2048,64,64,
                               1024,16,1024,16};
        const int offs[15]  = {JE_W1,JE_B1,JE_W2,JE_B2, MU_W1,MU_B1,MU_W2,MU_B2,
                               FC_W1,FC_B1,FC_W2, M1_W2,M1_B2,M2_W2,M2_B2};
        for (int a = 0; a < 15; a++) {
            const float* src = p.w[map[a]];
            float* dst = S + offs[a];
            int n = sizes[a];
            for (int i = threadIdx.x; i < n; i += NTHREADS) dst[i] = src[i];
        }
    }
    __syncthreads();

    int tid = threadIdx.x;
    int lane = tid & 31;
    int node = lane & 3;
    int group = lane >> 2;
    int warpG = (int)((blockIdx.x * (unsigned)NTHREADS + tid) >> 5);

    if (warpG * 16 >= p.G) return;   // warp-uniform

    int base = warpG * 16 + group;
    int gidx[NV], gc[NV];
    bool valid[NV];
#pragma unroll
    for (int nv = 0; nv < NV; nv++) {
        gidx[nv] = base + 8 * nv;
        valid[nv] = gidx[nv] < p.G;
        gc[nv] = valid[nv] ? gidx[nv] : (p.G - 1);
    }

    // ---- heterogeneous encoder (shared, node-divergent base) ----
    const float* w1p = (node == 3) ? (S + MU_W1) : (S + JE_W1);
    const float* b1p = (node == 3) ? (S + MU_B1) : (S + JE_B1);
    const float* w2p = (node == 3) ? (S + MU_W2) : (S + JE_W2);
    const float* b2p = (node == 3) ? (S + MU_B2) : (S + JE_B2);

    u64 h[NV][8];
    {
        float xin[NV][5];
#pragma unroll
        for (int nv = 0; nv < NV; nv++) {
            const float* xr = p.x + (long long)(gc[nv] * 4 + node) * 5;
#pragma unroll
            for (int k = 0; k < 5; k++) xin[nv][k] = __ldg(xr + k);
        }

        u64 tv[NV][8];
        {
            ulonglong2 a = ld2(b1p), b = ld2(b1p+4), c = ld2(b1p+8), d = ld2(b1p+12);
#pragma unroll
            for (int nv = 0; nv < NV; nv++) {
                tv[nv][0]=a.x; tv[nv][1]=a.y; tv[nv][2]=b.x; tv[nv][3]=b.y;
                tv[nv][4]=c.x; tv[nv][5]=c.y; tv[nv][6]=d.x; tv[nv][7]=d.y;
            }
        }
#pragma unroll
        for (int k = 0; k < 5; k++) {
            const float* r = w1p + k * 16;
            ulonglong2 wa = ld2(r), wb = ld2(r+4), wc = ld2(r+8), wd = ld2(r+12);
            u64 wv[8] = {wa.x,wa.y,wb.x,wb.y,wc.x,wc.y,wd.x,wd.y};
#pragma unroll
            for (int nv = 0; nv < NV; nv++) {
                u64 xp = pk(xin[nv][k], xin[nv][k]);
#pragma unroll
                for (int j = 0; j < 8; j++)
                    tv[nv][j] = f2(xp, wv[j], tv[nv][j]);
            }
        }

        {
            ulonglong2 a = ld2(b2p), b = ld2(b2p+4), c = ld2(b2p+8), d = ld2(b2p+12);
#pragma unroll
            for (int nv = 0; nv < NV; nv++) {
                h[nv][0]=a.x; h[nv][1]=a.y; h[nv][2]=b.x; h[nv][3]=b.y;
                h[nv][4]=c.x; h[nv][5]=c.y; h[nv][6]=d.x; h[nv][7]=d.y;
            }
        }
#pragma unroll
        for (int jp = 0; jp < 8; jp++) {
            u64 xlo[NV], xhi[NV];
#pragma unroll
            for (int nv = 0; nv < NV; nv++) {
                float a, b; up(tv[nv][jp], a, b);
                xlo[nv] = pk(fmaxf(a, 0.f), fmaxf(a, 0.f));
                xhi[nv] = pk(fmaxf(b, 0.f), fmaxf(b, 0.f));
            }
#pragma unroll
            for (int t = 0; t < 2; t++) {
                const float* r = w2p + (2 * jp + t) * 16;
                ulonglong2 wa = ld2(r), wb = ld2(r+4), wc = ld2(r+8), wd = ld2(r+12);
                u64 wv[8] = {wa.x,wa.y,wb.x,wb.y,wc.x,wc.y,wd.x,wd.y};
#pragma unroll
                for (int nv = 0; nv < NV; nv++) {
                    u64 xp = t ? xhi[nv] : xlo[nv];
#pragma unroll
                    for (int j = 0; j < 8; j++)
                        h[nv][j] = f2(xp, wv[j], h[nv][j]);
                }
            }
        }
    }

    // ---- two GINE blocks (split-port weights) ----
    gineN<cL1W, cL1B, cM1W1, cM1B1>(h, lane, node, p.ea, gc, S + M1_W2, S + M1_B2);
    gineN<cL2W, cL2B, cM2W1, cM2B1>(h, lane, node, p.ea, gc, S + M2_W2, S + M2_B2);

    // ---- pooling (packed shfl) + LN ----
    float g[NV][32];
#pragma unroll
    for (int nv = 0; nv < NV; nv++) {
#pragma unroll
        for (int j = 0; j < 8; j++) {
            u64 s = h[nv][j];
            s = a2(s, __shfl_xor_sync(0xffffffffu, s, 1));
            s = a2(s, __shfl_xor_sync(0xffffffffu, s, 2));
            float sa, sb; up(s, sa, sb);
            g[nv][2*j]   = sa * 0.25f;
            g[nv][2*j+1] = sb * 0.25f;

            u64 mx = h[nv][j];
            u64 o1 = __shfl_xor_sync(0xffffffffu, mx, 1);
            float a0, b0, a1, b1; up(mx, a0, b0); up(o1, a1, b1);
            mx = pk(fmaxf(a0, a1), fmaxf(b0, b1));
            u64 o2 = __shfl_xor_sync(0xffffffffu, mx, 2);
            up(mx, a0, b0); up(o2, a1, b1);
            g[nv][16 + 2*j]   = fmaxf(a0, a1);
            g[nv][16 + 2*j+1] = fmaxf(b0, b1);
        }
        float mean = 0.f;
#pragma unroll
        for (int d = 0; d < 32; d++) mean += g[nv][d];
        mean *= (1.f / 32.f);
        float var = 0.f;
#pragma unroll
        for (int d = 0; d < 32; d++) { float dd = g[nv][d] - mean; var = fmaf(dd, dd, var); }
        var *= (1.f / 32.f);
        float inv = rsqrtf(var + 1e-5f);
#pragma unroll
        for (int d = 0; d < 32; d++) g[nv][d] = (g[nv][d] - mean) * inv;
    }

    // ---- FC head: 32 -> 64 -> 1; node-divergent slices from shared ----
    u64 av[NV][8];
    {
        const float* r = S + FC_B1 + node * 16;
        ulonglong2 a = ld2(r), b = ld2(r+4), c = ld2(r+8), d = ld2(r+12);
#pragma unroll
        for (int nv = 0; nv < NV; nv++) {
            av[nv][0]=a.x; av[nv][1]=a.y; av[nv][2]=b.x; av[nv][3]=b.y;
            av[nv][4]=c.x; av[nv][5]=c.y; av[nv][6]=d.x; av[nv][7]=d.y;
        }
    }
#pragma unroll
    for (int k = 0; k < 32; k++) {
        const float* r = S + FC_W1 + k * 64 + node * 16;
        ulonglong2 wa = ld2(r), wb = ld2(r+4), wc = ld2(r+8), wd = ld2(r+12);
        u64 wv[8] = {wa.x,wa.y,wb.x,wb.y,wc.x,wc.y,wd.x,wd.y};
#pragma unroll
        for (int nv = 0; nv < NV; nv++) {
            u64 gp = pk(g[nv][k], g[nv][k]);
#pragma unroll
            for (int j = 0; j < 8; j++) av[nv][j] = f2(gp, wv[j], av[nv][j]);
        }
    }
    float acc[NV] = {0.f, 0.f};
#pragma unroll
    for (int j = 0; j < 8; j++) {
        float2 w2v = *reinterpret_cast<const float2*>(S + FC_W2 + node * 16 + 2 * j);
#pragma unroll
        for (int nv = 0; nv < NV; nv++) {
            float a, b; up(av[nv][j], a, b);
            acc[nv] = fmaf(fmaxf(a, 0.f), w2v.x, acc[nv]);
            acc[nv] = fmaf(fmaxf(b, 0.f), w2v.y, acc[nv]);
        }
    }
    const float fcb2 = __ldg(p.w[23]);
#pragma unroll
    for (int nv = 0; nv < NV; nv++) {
        acc[nv] += __shfl_xor_sync(0xffffffffu, acc[nv], 1);
        acc[nv] += __shfl_xor_sync(0xffffffffu, acc[nv], 2);
        if (node == 0 && valid[nv])
            p.out[gidx[nv]] = acc[nv] + fcb2;
    }
}

extern "C" void kernel_launch(void* const* d_in, const int* in_sizes, int n_in,
                              void* d_out, int out_size)
{
    Params p;
    p.x  = (const float*)d_in[0];
    p.ea = (const float*)d_in[1];
    for (int i = 0; i < 24; i++) p.w[i] = (const float*)d_in[2 + i];
    p.out = (float*)d_out;
    p.G = in_sizes[0] / 20;            // x is [G*4, 5]

    // Fill constant bank via its global-space address (graph-capturable).
    void* cw_addr = nullptr;
    cudaGetSymbolAddress(&cw_addr, CW);
    PackP pp;
    pp.src[0] = (const float*)d_in[10];  // lin1_w
    pp.src[1] = (const float*)d_in[11];  // lin1_b
    pp.src[2] = (const float*)d_in[12];  // m1_w1
    pp.src[3] = (const float*)d_in[13];  // m1_b1
    pp.src[4] = (const float*)d_in[16];  // lin2_w
    pp.src[5] = (const float*)d_in[17];  // lin2_b
    pp.src[6] = (const float*)d_in[18];  // m2_w1
    pp.src[7] = (const float*)d_in[19];  // m2_b1
    pp.dst = (float*)cw_addr;
    pack_kernel<<<1, 256>>>(pp);

    // 16 graphs per warp, 8 warps per block -> 128 graphs per block
    int blocks = (p.G + 127) / 128;
    if (blocks < 1) blocks = 1;
    gnn_kernel<<<blocks, NTHREADS>>>(p);
}